// round 12
// baseline (speedup 1.0000x reference)
#include <cuda_runtime.h>
#include <cuda_fp16.h>
#include <stdint.h>

#define HD    128
#define BB    64
#define LQ    64
#define LDOC  4096
#define NTILE 32               // 4096/128 doc tiles per batch
#define NQCTA 32               // query CTAs (4096 q-tokens / 128)
#define NDCTA 2048
#define NCTA  (NQCTA + NDCTA)
#define LN_EPS 1e-5f
#define NEGV  -1e30f

// ---------------- scratch (__device__ globals; no cudaMalloc) --------------
__device__ __half g_wt[4][HD * HD];                 // transposed fp16 weights
__device__ __half g_qv[(size_t)BB * LQ * HD];       // 1 MB, stored SWIZZLED
__device__ float  g_pmax[(size_t)BB * NTILE * LQ];  // 512 KB
__device__ int      g_prep_ctr;                     // query-CTA prep barrier
__device__ int      g_qready[BB];                   // per-batch query-done flag
__device__ int      g_batchfin[BB];                 // per-batch doc-CTA arrivals
__device__ unsigned g_fin;                          // monotone global arrivals

// ---------------- helpers ---------------------------------------------------
__device__ __forceinline__ uint32_t smem_u32(const void* p) {
    uint32_t a;
    asm("{ .reg .u64 t; cvta.to.shared.u64 t, %1; cvt.u32.u64 %0, t; }"
        : "=r"(a) : "l"(p));
    return a;
}

__device__ __forceinline__ void ldsm_x4(uint32_t& r0, uint32_t& r1,
                                        uint32_t& r2, uint32_t& r3, uint32_t a) {
    asm volatile("ldmatrix.sync.aligned.m8n8.x4.shared.b16 {%0,%1,%2,%3}, [%4];"
                 : "=r"(r0), "=r"(r1), "=r"(r2), "=r"(r3) : "r"(a));
}

__device__ __forceinline__ void mma16816(float* c,
                                         uint32_t a0, uint32_t a1, uint32_t a2,
                                         uint32_t a3, uint32_t b0, uint32_t b1) {
    asm volatile(
        "mma.sync.aligned.m16n8k16.row.col.f32.f16.f16.f32 "
        "{%0,%1,%2,%3}, {%4,%5,%6,%7}, {%8,%9}, {%0,%1,%2,%3};"
        : "+f"(c[0]), "+f"(c[1]), "+f"(c[2]), "+f"(c[3])
        : "r"(a0), "r"(a1), "r"(a2), "r"(a3), "r"(b0), "r"(b1));
}

__device__ __forceinline__ uint32_t pack2(float a, float b) {
    __half2 h = __floats2half2_rn(a, b);
    return *(uint32_t*)&h;
}

// swizzled smem offset for (row, 16B-chunk) in a [rows][256B] fp16 tile
__device__ __forceinline__ uint32_t swz(int row, int chunk) {
    return (uint32_t)(row * 256 + ((chunk ^ (row & 7)) * 16));
}

// ---------------- single fused kernel --------------------------------------
// 128 threads = 4 warps, M=32 token rows per warp. ONE weight buffer
// (reloaded between stages) -> 68 KB SMEM -> 3 CTAs/SM.
#define ESM_X   0
#define ESM_W   32768
#define ESM_P   65536
#define ESM_RED 67584
#define ESM_TOTAL 68608

__device__ __forceinline__ void init_bias(float (&acc)[2][16][4],
                                          const float* __restrict__ sB, int q4) {
#pragma unroll
    for (int nt = 0; nt < 16; nt++) {
        const float2 bc = *(const float2*)(sB + nt * 8 + 2 * q4);
#pragma unroll
        for (int mt = 0; mt < 2; mt++) {
            acc[mt][nt][0] = bc.x; acc[mt][nt][1] = bc.y;
            acc[mt][nt][2] = bc.x; acc[mt][nt][3] = bc.y;
        }
    }
}

// A from SMEM tile Xb, B double-buffered from Wb
__device__ __forceinline__ void mma_A_smem(float (&acc)[2][16][4],
                                           uint32_t Xb, uint32_t Wb,
                                           int lane, int wrow) {
    const int arow  = wrow + (lane & 7) + ((lane >> 3) & 1) * 8;
    const int akc   = (lane >> 4) & 1;
    const int brow0 = (lane & 7) + ((lane >> 4) & 1) * 8;
    const int bkc   = (lane >> 3) & 1;
#pragma unroll
    for (int kk = 0; kk < 8; kk++) {
        uint32_t a0[4], a1[4];
        ldsm_x4(a0[0], a0[1], a0[2], a0[3], Xb + swz(arow,      kk * 2 + akc));
        ldsm_x4(a1[0], a1[1], a1[2], a1[3], Xb + swz(arow + 16, kk * 2 + akc));
        uint32_t bc_[2][4];
        ldsm_x4(bc_[0][0], bc_[0][1], bc_[0][2], bc_[0][3],
                Wb + swz(brow0, kk * 2 + bkc));
#pragma unroll
        for (int nt2 = 0; nt2 < 8; nt2++) {
            const int cur = nt2 & 1, nxt = cur ^ 1;
            if (nt2 < 7)
                ldsm_x4(bc_[nxt][0], bc_[nxt][1], bc_[nxt][2], bc_[nxt][3],
                        Wb + swz((nt2 + 1) * 16 + brow0, kk * 2 + bkc));
            mma16816(acc[0][2 * nt2],     a0[0], a0[1], a0[2], a0[3],
                     bc_[cur][0], bc_[cur][1]);
            mma16816(acc[0][2 * nt2 + 1], a0[0], a0[1], a0[2], a0[3],
                     bc_[cur][2], bc_[cur][3]);
            mma16816(acc[1][2 * nt2],     a1[0], a1[1], a1[2], a1[3],
                     bc_[cur][0], bc_[cur][1]);
            mma16816(acc[1][2 * nt2 + 1], a1[0], a1[1], a1[2], a1[3],
                     bc_[cur][2], bc_[cur][3]);
        }
    }
}

// ReLU + LayerNorm (+opt mask); result written to SMEM X as fp16
__device__ __forceinline__ void epilogue(float (&acc)[2][16][4],
                                         const float* __restrict__ sLW,
                                         const float* __restrict__ sLB,
                                         int lane, int wrow,
                                         const int* __restrict__ mrow,
                                         char* __restrict__ smem) {
    const int g = lane >> 2, q4 = lane & 3;
#pragma unroll
    for (int mt = 0; mt < 2; mt++) {
        float s0 = 0.f, ss0 = 0.f, s1 = 0.f, ss1 = 0.f;
#pragma unroll
        for (int nt = 0; nt < 16; nt++) {
            float v0 = fmaxf(acc[mt][nt][0], 0.f);
            float v1 = fmaxf(acc[mt][nt][1], 0.f);
            float v2 = fmaxf(acc[mt][nt][2], 0.f);
            float v3 = fmaxf(acc[mt][nt][3], 0.f);
            acc[mt][nt][0] = v0; acc[mt][nt][1] = v1;
            acc[mt][nt][2] = v2; acc[mt][nt][3] = v3;
            s0 += v0 + v1; ss0 += v0 * v0 + v1 * v1;
            s1 += v2 + v3; ss1 += v2 * v2 + v3 * v3;
        }
#pragma unroll
        for (int o = 1; o <= 2; o <<= 1) {
            s0  += __shfl_xor_sync(0xffffffffu, s0,  o);
            ss0 += __shfl_xor_sync(0xffffffffu, ss0, o);
            s1  += __shfl_xor_sync(0xffffffffu, s1,  o);
            ss1 += __shfl_xor_sync(0xffffffffu, ss1, o);
        }
        const int r0 = wrow + mt * 16 + g, r1 = r0 + 8;
        const float mean0 = s0 * (1.0f / HD);
        const float mean1 = s1 * (1.0f / HD);
        const float rstd0 = rsqrtf(ss0 * (1.0f / HD) - mean0 * mean0 + LN_EPS);
        const float rstd1 = rsqrtf(ss1 * (1.0f / HD) - mean1 * mean1 + LN_EPS);
        const float mv0 = mrow ? (float)mrow[r0] : 1.0f;
        const float mv1 = mrow ? (float)mrow[r1] : 1.0f;
#pragma unroll
        for (int nt = 0; nt < 16; nt++) {
            const float2 lw = *(const float2*)(sLW + nt * 8 + 2 * q4);
            const float2 lb = *(const float2*)(sLB + nt * 8 + 2 * q4);
            float y0 = ((acc[mt][nt][0] - mean0) * rstd0 * lw.x + lb.x) * mv0;
            float y1 = ((acc[mt][nt][1] - mean0) * rstd0 * lw.y + lb.y) * mv0;
            float y2 = ((acc[mt][nt][2] - mean1) * rstd1 * lw.x + lb.x) * mv1;
            float y3 = ((acc[mt][nt][3] - mean1) * rstd1 * lw.y + lb.y) * mv1;
            *(uint32_t*)(smem + ESM_X + swz(r0, nt) + 4 * q4) = pack2(y0, y1);
            *(uint32_t*)(smem + ESM_X + swz(r1, nt) + 4 * q4) = pack2(y2, y3);
        }
    }
    __syncwarp();
}

__device__ __forceinline__ void load_w(char* __restrict__ smem,
                                       const __half* __restrict__ src, int tid) {
    const uint4* w = (const uint4*)src;
#pragma unroll
    for (int i = 0; i < 16; i++) {
        int idx = tid + i * 128;       // 2048 chunks
        int r = idx >> 4, c = idx & 15;
        *(uint4*)(smem + ESM_W + swz(r, c)) = w[idx];
    }
}

__global__ __launch_bounds__(128, 3)
void colbert_all(const int* __restrict__ qids, const int* __restrict__ dids,
                 const int* __restrict__ qmask, const int* __restrict__ dmask,
                 const float* __restrict__ q_emb,
                 const float* __restrict__ qW1, const float* __restrict__ qb1,
                 const float* __restrict__ qW2, const float* __restrict__ qb2,
                 const float* __restrict__ q_lnw, const float* __restrict__ q_lnb,
                 const float* __restrict__ d_emb,
                 const float* __restrict__ dW1, const float* __restrict__ db1,
                 const float* __restrict__ dW2, const float* __restrict__ db2,
                 const float* __restrict__ d_lnw, const float* __restrict__ d_lnb,
                 float* __restrict__ out)
{
    extern __shared__ __align__(16) char smem[];
    const int bid = blockIdx.x;
    const int tid = threadIdx.x, wid = tid >> 5, lane = tid & 31;
    const bool isq = (bid < NQCTA);
    const uint32_t sb = smem_u32(smem);
    float* sP = (float*)(smem + ESM_P);

    const int*   ids  = isq ? qids  : dids;
    const int*   mask = isq ? qmask : dmask;
    const float* emb  = isq ? q_emb : d_emb;
    const float* b1   = isq ? qb1   : db1;
    const float* b2   = isq ? qb2   : db2;
    const float* lnw  = isq ? q_lnw : d_lnw;
    const float* lnb  = isq ? q_lnb : d_lnb;
    const int    mat0 = isq ? 2 : 0;
    const int    dcta = bid - NQCTA;                // doc tile index
    const size_t tokbase = (size_t)(isq ? bid : dcta) * 128;

    // ---- query CTAs: cooperative weight prep (transpose + fp16) ----------
    if (isq) {
        const float* Ws[4] = {dW1, dW2, qW1, qW2};
        const int i0 = bid * 2048 + tid * 16;
#pragma unroll
        for (int k = 0; k < 16; k++) {
            int i = i0 + k;
            int mat = i >> 14, r = i & 16383, j = r >> 7, kc = r & 127;
            g_wt[mat][j * HD + kc] = __float2half_rn(Ws[mat][kc * HD + j]);
        }
        __threadfence();
        __syncthreads();
        if (tid == 0) atomicAdd(&g_prep_ctr, 1);
    }

    sP[tid]       = b1[tid];
    sP[128 + tid] = b2[tid];
    sP[256 + tid] = lnw[tid];
    sP[384 + tid] = lnb[tid];

    // embedding gather: 1 thread per token (independent of prep)
    {
        const int id = ids[tokbase + tid];
        const float4* er = (const float4*)(emb + (size_t)id * HD);
#pragma unroll
        for (int c = 0; c < 16; c++) {
            float4 fa = er[2 * c], fb = er[2 * c + 1];
            *(uint4*)(smem + ESM_X + swz(tid, c)) =
                make_uint4(pack2(fa.x, fa.y), pack2(fa.z, fa.w),
                           pack2(fb.x, fb.y), pack2(fb.z, fb.w));
        }
    }

    // wait for weight prep (query CTAs 0-31 are wave-1 resident -> no deadlock)
    if (tid == 0) {
        while (atomicAdd(&g_prep_ctr, 0) < NQCTA) { }
    }
    __syncthreads();
    __threadfence();

    load_w(smem, g_wt[mat0], tid);
    __syncthreads();

    const int wrow = wid * 32;
    float acc[2][16][4];

    // ---- layer 1 ----
    init_bias(acc, sP, lane & 3);
    mma_A_smem(acc, sb + ESM_X, sb + ESM_W, lane, wrow);
    epilogue(acc, sP + 256, sP + 384, lane, wrow, nullptr, smem);
    __syncthreads();           // all warps done reading W (=W1)

    load_w(smem, g_wt[mat0 + 1], tid);   // W <- W2
    __syncthreads();

    // ---- layer 2 ----
    init_bias(acc, sP + 128, lane & 3);
    mma_A_smem(acc, sb + ESM_X, sb + ESM_W, lane, wrow);
    epilogue(acc, sP + 256, sP + 384, lane, wrow,
             isq ? (mask + tokbase) : nullptr, smem);

    if (isq) {
        __syncthreads();
        uint4* gdst = (uint4*)g_qv + (size_t)bid * 2048;
#pragma unroll
        for (int i = 0; i < 16; i++)
            gdst[tid + i * 128] = ((const uint4*)(smem + ESM_X))[tid + i * 128];
        __threadfence();
        __syncthreads();
        if (tid == 0) {        // this CTA covered batches 2*bid, 2*bid+1
            atomicExch(&g_qready[2 * bid],     1);
            atomicExch(&g_qready[2 * bid + 1], 1);
            unsigned old = atomicAdd(&g_fin, 1u);
            if (((old + 1) % NCTA) == 0) {     // globally last CTA: reset flags
                g_prep_ctr = 0;
                for (int b = 0; b < BB; b++) g_qready[b] = 0;
            }
        }
        return;
    }

    const int b = dcta >> 5;   // batch
    __syncthreads();           // all warps done reading W (=W2)

    // wait for this batch's queries, then stage Q tile into W
    if (tid == 0) {
        while (atomicAdd(&g_qready[b], 0) == 0) { }
    }
    __syncthreads();
    __threadfence();
    {
        const uint4* qs = (const uint4*)(g_qv + (size_t)b * LQ * HD);
#pragma unroll
        for (int i = 0; i < 8; i++)
            ((uint4*)(smem + ESM_W))[tid + i * 128] = qs[tid + i * 128];
    }
    __syncthreads();

    // ---- fused maxsim: D[128 docs] x Q[64 queries], K=128 ----
    float sa[2][8][4];
#pragma unroll
    for (int mt = 0; mt < 2; mt++)
#pragma unroll
        for (int nt = 0; nt < 8; nt++) {
            sa[mt][nt][0] = 0.f; sa[mt][nt][1] = 0.f;
            sa[mt][nt][2] = 0.f; sa[mt][nt][3] = 0.f;
        }
    {
        const int arow  = wrow + (lane & 7) + ((lane >> 3) & 1) * 8;
        const int akc   = (lane >> 4) & 1;
        const int brow0 = (lane & 7) + ((lane >> 4) & 1) * 8;
        const int bkc   = (lane >> 3) & 1;
#pragma unroll
        for (int kk = 0; kk < 8; kk++) {
            uint32_t a0[4], a1[4];
            ldsm_x4(a0[0], a0[1], a0[2], a0[3],
                    sb + ESM_X + swz(arow,      kk * 2 + akc));
            ldsm_x4(a1[0], a1[1], a1[2], a1[3],
                    sb + ESM_X + swz(arow + 16, kk * 2 + akc));
            uint32_t bc_[2][4];
            ldsm_x4(bc_[0][0], bc_[0][1], bc_[0][2], bc_[0][3],
                    sb + ESM_W + swz(brow0, kk * 2 + bkc));
#pragma unroll
            for (int nt2 = 0; nt2 < 4; nt2++) {
                const int cur = nt2 & 1, nxt = cur ^ 1;
                if (nt2 < 3)
                    ldsm_x4(bc_[nxt][0], bc_[nxt][1], bc_[nxt][2], bc_[nxt][3],
                            sb + ESM_W + swz((nt2 + 1) * 16 + brow0, kk * 2 + bkc));
                mma16816(sa[0][2 * nt2],     a0[0], a0[1], a0[2], a0[3],
                         bc_[cur][0], bc_[cur][1]);
                mma16816(sa[0][2 * nt2 + 1], a0[0], a0[1], a0[2], a0[3],
                         bc_[cur][2], bc_[cur][3]);
                mma16816(sa[1][2 * nt2],     a1[0], a1[1], a1[2], a1[3],
                         bc_[cur][0], bc_[cur][1]);
                mma16816(sa[1][2 * nt2 + 1], a1[0], a1[1], a1[2], a1[3],
                         bc_[cur][2], bc_[cur][3]);
            }
        }
    }

    // penalties + max over this warp's 32 doc rows
    const int g = lane >> 2;
    int r4[4] = {wrow + g, wrow + g + 8, wrow + 16 + g, wrow + 24 + g};
    float p[4];
#pragma unroll
    for (int j = 0; j < 4; j++)
        p[j] = (1.0f - (float)dmask[tokbase + r4[j]]) * NEGV;

    float* red = (float*)(smem + ESM_RED);
#pragma unroll
    for (int nt = 0; nt < 8; nt++) {
        float v0 = -3.0e38f, v1 = -3.0e38f;
#pragma unroll
        for (int j = 0; j < 4; j++) {
            const int mt = j >> 1, h = j & 1;
            v0 = fmaxf(v0, sa[mt][nt][2 * h]     + p[j]);
            v1 = fmaxf(v1, sa[mt][nt][2 * h + 1] + p[j]);
        }
#pragma unroll
        for (int o = 4; o <= 16; o <<= 1) {
            v0 = fmaxf(v0, __shfl_xor_sync(0xffffffffu, v0, o));
            v1 = fmaxf(v1, __shfl_xor_sync(0xffffffffu, v1, o));
        }
        if (lane < 4)
            *(float2*)(red + wid * 64 + nt * 8 + 2 * lane) = make_float2(v0, v1);
    }
    __syncthreads();
    if (tid < 64) {
        float m = red[tid];
#pragma unroll
        for (int w = 1; w < 4; w++) m = fmaxf(m, red[w * 64 + tid]);
        g_pmax[(size_t)dcta * 64 + tid] = m;
    }
    __threadfence();
    __syncthreads();

    // ---- last doc CTA of this batch: final max-over-tiles + sum ----------
    __shared__ int s_win;
    if (tid == 0) s_win = (atomicAdd(&g_batchfin[b], 1) == NTILE - 1) ? 1 : 0;
    __syncthreads();
    if (s_win) {
        __threadfence();
        float m = -3.0e38f;
        if (tid < 64) {
#pragma unroll
            for (int t = 0; t < NTILE; t++)
                m = fmaxf(m, g_pmax[((size_t)b * NTILE + t) * LQ + tid]);
            float s = m;
#pragma unroll
            for (int o = 16; o > 0; o >>= 1)
                s += __shfl_xor_sync(0xffffffffu, s, o);
            if ((tid & 31) == 0) red[tid >> 5] = s;
        }
        __syncthreads();
        if (tid == 0) {
            out[b] = red[0] + red[1];
            g_batchfin[b] = 0;          // reset for next graph replay
            __threadfence();
        }
    }
    if (tid == 0) {
        unsigned old = atomicAdd(&g_fin, 1u);
        if (((old + 1) % NCTA) == 0) {  // globally last CTA: reset flags
            g_prep_ctr = 0;
            for (int bb = 0; bb < BB; bb++) g_qready[bb] = 0;
        }
    }
}

// ---------------- launch ---------------------------------------------------
extern "C" void kernel_launch(void* const* d_in, const int* in_sizes, int n_in,
                              void* d_out, int out_size)
{
    const int*   qids  = (const int*)d_in[0];
    const int*   dids  = (const int*)d_in[1];
    const int*   qmask = (const int*)d_in[2];
    const int*   dmask = (const int*)d_in[3];
    const float* q_emb = (const float*)d_in[4];
    const float* qW1   = (const float*)d_in[5];
    const float* qb1   = (const float*)d_in[6];
    const float* qW2   = (const float*)d_in[7];
    const float* qb2   = (const float*)d_in[8];
    const float* q_lnw = (const float*)d_in[9];
    const float* q_lnb = (const float*)d_in[10];
    const float* d_emb = (const float*)d_in[11];
    const float* dW1   = (const float*)d_in[12];
    const float* db1   = (const float*)d_in[13];
    const float* dW2   = (const float*)d_in[14];
    const float* db2   = (const float*)d_in[15];
    const float* d_lnw = (const float*)d_in[16];
    const float* d_lnb = (const float*)d_in[17];
    float* out = (float*)d_out;

    cudaFuncSetAttribute(colbert_all,
        cudaFuncAttributeMaxDynamicSharedMemorySize, ESM_TOTAL);

    colbert_all<<<NCTA, 128, ESM_TOTAL>>>(
        qids, dids, qmask, dmask,
        q_emb, qW1, qb1, qW2, qb2, q_lnw, q_lnb,
        d_emb, dW1, db1, dW2, db2, d_lnw, d_lnb, out);
}